// round 17
// baseline (speedup 1.0000x reference)
#include <cuda_runtime.h>
#include <cuda_bf16.h>
#include <cuda_fp16.h>
#include <math.h>
#include <stdint.h>

#define D_MODEL   256
#define D_INNER   512
#define CONV_CH   640
#define SEQ       64
#define NSEQ      512
#define NTOK      32768
#define KFIN      1024
#define NIN       1152

// ---------------- scratch ------------------------------------------------------
__device__ __half g_Z16h[(size_t)NTOK * D_INNER];
__device__ __half g_Z16v[(size_t)NTOK * D_INNER];
__device__ float  g_dth [(size_t)NTOK * 8];
__device__ float  g_dtv [(size_t)NTOK * 8];
__device__ __half g_XBCh[(size_t)NTOK * CONV_CH];
__device__ __half g_XBCv[(size_t)NTOK * CONV_CH];
__device__ __half g_Xhi [(size_t)NTOK * D_MODEL];
__device__ __half g_Whhi[(size_t)NIN * D_MODEL];
__device__ __half g_Wvhi[(size_t)NIN * D_MODEL];
__device__ __half g_Y   [(size_t)NTOK * KFIN];
__device__ __half g_WcBhi[(size_t)D_MODEL * KFIN];

extern __shared__ char dynsm[];

// ---------------- helpers ------------------------------------------------------
__device__ __forceinline__ uint32_t smem_u32(const void* p) {
    uint32_t a;
    asm("{ .reg .u64 t; cvta.to.shared.u64 t, %1; cvt.u32.u64 %0, t; }" : "=r"(a) : "l"(p));
    return a;
}
__device__ __forceinline__ uint32_t swz128(uint32_t off) {
    return off ^ ((off >> 3) & 0x70);
}
#define CP16(dst, src) \
    asm volatile("cp.async.cg.shared.global [%0], [%1], 16;" :: "r"(dst), "l"(src))
#define CP_COMMIT() asm volatile("cp.async.commit_group;" ::: "memory")
#define CP_WAIT(n)  asm volatile("cp.async.wait_group %0;" :: "n"(n) : "memory")

__device__ __forceinline__ void ldm4(uint32_t* r, uint32_t addr) {
    asm volatile("ldmatrix.sync.aligned.m8n8.x4.shared.b16 {%0,%1,%2,%3}, [%4];"
        : "=r"(r[0]), "=r"(r[1]), "=r"(r[2]), "=r"(r[3]) : "r"(addr));
}
__device__ __forceinline__ void mma16816(float* d, const uint32_t* a, uint32_t b0, uint32_t b1) {
    asm volatile("mma.sync.aligned.m16n8k16.row.col.f32.f16.f16.f32 "
        "{%0,%1,%2,%3}, {%4,%5,%6,%7}, {%8,%9}, {%0,%1,%2,%3};"
        : "+f"(d[0]), "+f"(d[1]), "+f"(d[2]), "+f"(d[3])
        : "r"(a[0]), "r"(a[1]), "r"(a[2]), "r"(a[3]), "r"(b0), "r"(b1));
}

// ---------------- merged prep kernel ---------------------------------------------
// blocks [0,1152): in-proj weight fp16 convert
// blocks [1152,1408): wcomb (fold fc into out_w, fp16)
// blocks [1408,2432): cvt x->fp16 + exact fp32 dt
#define PREP_GRID (1152 + 256 + 1024)

__global__ void __launch_bounds__(256) prep_all(
    const float* __restrict__ x,
    const float* __restrict__ mh_in_w, const float* __restrict__ mv_in_w,
    const float* __restrict__ mh_out_w, const float* __restrict__ mv_out_w,
    const float* __restrict__ fc_w)
{
    __shared__ __align__(16) char pbuf[49920];
    const int tid = threadIdx.x;
    int blk = blockIdx.x;

    if (blk < 1152) {
        int i = blk * 256 + tid;
        g_Whhi[i] = __float2half(mh_in_w[i]);
        g_Wvhi[i] = __float2half(mv_in_w[i]);
        return;
    }
    blk -= 1152;

    if (blk < 256) {
        // ---- wcomb: WcBhi[n][d*512+k] = sum_j ow[j][k]*(fc[n][fo+j]+fc[n][fo+256+j])
        float (*ows)[33] = (float(*)[33])pbuf;             // [64][33]
        float (*fs)[65]  = (float(*)[65])(pbuf + 8448);    // [32][65]
        const int d  = blk & 1;
        const int rest = blk >> 1;
        const int k0 = (rest & 15) * 32;
        const int nb = (rest >> 4) * 32;
        const float* ow = d ? mh_out_w : mv_out_w;
        const int fo = d ? 512 : 0;
        const int kk = tid & 31;
        const int ng = tid >> 5;
        float acc[4];
#pragma unroll
        for (int i = 0; i < 4; i++) acc[i] = 0.f;

        for (int jo = 0; jo < 256; jo += 64) {
            for (int idx = tid; idx < 64 * 32; idx += 256) {
                int j = idx >> 5, k = idx & 31;
                ows[j][k] = ow[(size_t)(jo + j) * 512 + k0 + k];
            }
            for (int idx = tid; idx < 32 * 64; idx += 256) {
                int n = idx >> 6, jj = idx & 63;
                fs[n][jj] = fc_w[(size_t)(nb + n) * 1024 + fo + jo + jj] +
                            fc_w[(size_t)(nb + n) * 1024 + fo + 256 + jo + jj];
            }
            __syncthreads();
#pragma unroll 4
            for (int j = 0; j < 64; j++) {
                float o = ows[j][kk];
#pragma unroll
                for (int i = 0; i < 4; i++)
                    acc[i] = fmaf(o, fs[ng * 4 + i][j], acc[i]);
            }
            __syncthreads();
        }
#pragma unroll
        for (int i = 0; i < 4; i++)
            g_WcBhi[(size_t)(nb + ng * 4 + i) * KFIN + d * 512 + (k0 + kk)] = __float2half(acc[i]);
        return;
    }
    blk -= 256;

    // ---- cvtdt: x -> fp16 Xhi + exact fp32 dt (both dirs)
    float (*xs)[260] = (float(*)[260])pbuf;                     // [32][260]
    float (*wh)[260] = (float(*)[260])(pbuf + 32 * 260 * 4);    // [8][260]
    float (*wv)[260] = (float(*)[260])(pbuf + 40 * 260 * 4);    // [8][260]
    const float* whd = mh_in_w + 1152 * 256;
    const float* wvd = mv_in_w + 1152 * 256;
    const int row0 = blk * 32;
    for (int i = tid; i < 8 * 64; i += 256) {
        int h = i >> 6, c4 = (i & 63) * 4;
        *(float4*)&wh[h][c4] = *(const float4*)&whd[h * 256 + c4];
        *(float4*)&wv[h][c4] = *(const float4*)&wvd[h * 256 + c4];
    }
    for (int i = tid; i < 32 * 64; i += 256) {
        int r = i >> 6, c4 = (i & 63) * 4;
        *(float4*)&xs[r][c4] = *(const float4*)&x[(size_t)(row0 + r) * 256 + c4];
    }
    __syncthreads();
    for (int i = tid; i < 32 * 64; i += 256) {
        int r = i >> 6, c4 = (i & 63) * 4;
        float4 v = *(float4*)&xs[r][c4];
        size_t o = ((size_t)(row0 + r) * 256 + c4) >> 1;
        ((__half2*)g_Xhi)[o]     = __floats2half2_rn(v.x, v.y);
        ((__half2*)g_Xhi)[o + 1] = __floats2half2_rn(v.z, v.w);
    }
    const int r = tid >> 3, h = tid & 7;
    float ah = 0.f, av = 0.f;
#pragma unroll 8
    for (int k = 0; k < 256; k += 4) {
        float4 xv = *(float4*)&xs[r][k];
        float4 wa = *(float4*)&wh[h][k];
        float4 wb = *(float4*)&wv[h][k];
        ah = fmaf(xv.x, wa.x, ah); ah = fmaf(xv.y, wa.y, ah);
        ah = fmaf(xv.z, wa.z, ah); ah = fmaf(xv.w, wa.w, ah);
        av = fmaf(xv.x, wb.x, av); av = fmaf(xv.y, wb.y, av);
        av = fmaf(xv.z, wb.z, av); av = fmaf(xv.w, wb.w, av);
    }
    g_dth[(size_t)(row0 + r) * 8 + h] = ah;
    g_dtv[(size_t)(row0 + r) * 8 + h] = av;
}

// ---------------- mma.sync fp16 GEMM, 1-term, BK=64, 3-stage --------------------
#define BMg 128
#define BNg 128
#define TILE64_B 16384
#define STAGE_B  32768
#define GSMEM    98304

__global__ void __launch_bounds__(256, 2) gemm_mma(
    const __half* __restrict__ A,
    const __half* __restrict__ B0, const __half* __restrict__ B1,
    float* __restrict__ C,
    __half* __restrict__ Z0, __half* __restrict__ X0,
    __half* __restrict__ Z1, __half* __restrict__ X1,
    int K, int ldc, const float* __restrict__ bias, int mode)
{
    const uint32_t smb = smem_u32(dynsm);
    const int tid = threadIdx.x, lane = tid & 31, wid = tid >> 5;
    const int m0 = blockIdx.x * BMg, n0 = blockIdx.y * BNg;
    const int wm = (wid & 1) * 64, wn = 32 * (wid >> 1);
    const int nk = K >> 6;

    const __half* B = blockIdx.z ? B1 : B0;
    __half* Z16 = blockIdx.z ? Z1 : Z0;
    __half* XB  = blockIdx.z ? X1 : X0;

    uint32_t arow[4], brow[2];
#pragma unroll
    for (int mt = 0; mt < 4; mt++)
        arow[mt] = (uint32_t)(wm + mt * 16 + (lane & 15)) * 128 + (lane >> 4) * 16;
#pragma unroll
    for (int nb = 0; nb < 2; nb++)
        brow[nb] = (uint32_t)(wn + nb * 16 + (lane & 15)) * 128 + (lane >> 4) * 16;

    float acc[4][4][4];
#pragma unroll
    for (int a = 0; a < 4; a++)
#pragma unroll
        for (int b = 0; b < 4; b++)
#pragma unroll
            for (int c = 0; c < 4; c++) acc[a][b][c] = 0.f;

    const int lrow = tid >> 1, cq = (tid & 1) * 4;

    auto load_stage = [&](int s, int c) {
        const int koff = c * 64;
        const uint32_t base = smb + s * STAGE_B;
        const __half* pA = A + (size_t)(m0 + lrow) * K + koff;
        const __half* pB = B + (size_t)(n0 + lrow) * K + koff;
        const uint32_t rb = (uint32_t)lrow * 128;
#pragma unroll
        for (int ch = 0; ch < 4; ch++) {
            uint32_t d = swz128(rb + (cq + ch) * 16);
            CP16(base + d, pA + (cq + ch) * 8);
            CP16(base + TILE64_B + d, pB + (cq + ch) * 8);
        }
        CP_COMMIT();
    };

    load_stage(0, 0);
    load_stage(1, 1);

    for (int c = 0; c < nk; c++) {
        if (c + 1 < nk) CP_WAIT(1); else CP_WAIT(0);
        __syncthreads();
        if (c + 2 < nk) load_stage((c + 2) % 3, c + 2);

        const uint32_t base = smb + (c % 3) * STAGE_B;
        const uint32_t aB = base, bB = base + TILE64_B;
#pragma unroll
        for (int ks = 0; ks < 4; ks++) {
            uint32_t af[4][4], bf[2][4];
#pragma unroll
            for (int mt = 0; mt < 4; mt++)
                ldm4(af[mt], aB + swz128(arow[mt] + ks * 32));
#pragma unroll
            for (int nb = 0; nb < 2; nb++)
                ldm4(bf[nb], bB + swz128(brow[nb] + ks * 32));
#pragma unroll
            for (int mt = 0; mt < 4; mt++)
#pragma unroll
                for (int nb = 0; nb < 2; nb++) {
                    mma16816(acc[mt][nb * 2],     af[mt], bf[nb][0], bf[nb][2]);
                    mma16816(acc[mt][nb * 2 + 1], af[mt], bf[nb][1], bf[nb][3]);
                }
        }
    }

#pragma unroll
    for (int mt = 0; mt < 4; mt++) {
        int row = m0 + wm + mt * 16 + (lane >> 2);
#pragma unroll
        for (int nt = 0; nt < 4; nt++) {
            int col = n0 + wn + nt * 8 + (lane & 3) * 2;
            float2 v0 = make_float2(acc[mt][nt][0], acc[mt][nt][1]);
            float2 v1 = make_float2(acc[mt][nt][2], acc[mt][nt][3]);
            if (mode == 1) {
                if (col < 512) {
                    *(__half2*)&Z16[(size_t)row * 512 + col]       = __floats2half2_rn(v0.x, v0.y);
                    *(__half2*)&Z16[(size_t)(row + 8) * 512 + col] = __floats2half2_rn(v1.x, v1.y);
                } else {
                    int xc = col - 512;
                    *(__half2*)&XB[(size_t)row * 640 + xc]       = __floats2half2_rn(v0.x, v0.y);
                    *(__half2*)&XB[(size_t)(row + 8) * 640 + xc] = __floats2half2_rn(v1.x, v1.y);
                }
            } else {
                float b0 = bias[col], b1 = bias[col + 1];
                v0.x += b0; v0.y += b1; v1.x += b0; v1.y += b1;
                *(float2*)&C[(size_t)row * ldc + col] = v0;
                *(float2*)&C[(size_t)(row + 8) * ldc + col] = v1;
            }
        }
    }
}

// ---------------- SSD kernel ----------------------------------------------------
#define RAW_PITCH 1296
#define XDT_PITCH 144
#define G_PITCH   68
#define GSM_PITCH 520

#define GSM_OFF   0
#define G_OFF     66560
#define XDT_OFF   86832
#define BM_OFF    160560
#define CM_OFF    169776
#define GMH_OFF   178992
#define GML_OFF   188208
#define ZBUF_OFF  197424
#define L_OFF     213808
#define DTS_OFF   215856
#define DDT_OFF   217904
#define NW_OFF    219952
#define SSD_SMEM  222000

__global__ void __launch_bounds__(512, 1) ssd_kernel(
    const float* __restrict__ cwh, const float* __restrict__ cbh,
    const float* __restrict__ dtbh, const float* __restrict__ Alh,
    const float* __restrict__ Dh_, const float* __restrict__ nwh,
    const float* __restrict__ cwv, const float* __restrict__ cbv,
    const float* __restrict__ dtbv, const float* __restrict__ Alv,
    const float* __restrict__ Dv_, const float* __restrict__ nwv)
{
    char* sm = dynsm;
    const uint32_t smb = smem_u32(sm);
    const int tid = threadIdx.x, lane = tid & 31, wid = tid >> 5;
    const int dir = blockIdx.x >> 9;
    const int s   = blockIdx.x & 511;

    const __half* Z16     = dir ? g_Z16v : g_Z16h;
    const float*  DT      = dir ? g_dtv : g_dth;
    const __half* XBC     = dir ? g_XBCv : g_XBCh;
    const float*  conv_w  = dir ? cwv : cwh;
    const float*  conv_b  = dir ? cbv : cbh;
    const float*  dt_bias = dir ? dtbv : dtbh;
    const float*  A_log   = dir ? Alv : Alh;
    const float*  Dv      = dir ? Dv_ : Dh_;
    const float*  norm_w  = dir ? nwv : nwh;
    const int ycol = dir ? 0 : 512;

    int base, stride;
    if (dir) { int b = s >> 6, w = s & 63; base = b * 4096 + w; stride = 64; }
    else     { base = s * 64; stride = 1; }

    __half* XdT = (__half*)(sm + XDT_OFF);
    __half* Bm  = (__half*)(sm + BM_OFF);
    __half* Cm  = (__half*)(sm + CM_OFF);
    float*  G   = (float*)(sm + G_OFF);
    float*  Lc  = (float*)(sm + L_OFF);
    float*  dts = (float*)(sm + DTS_OFF);
    float*  Ddt = (float*)(sm + DDT_OFF);
    float*  nws = (float*)(sm + NW_OFF);
    __half* gsm = (__half*)(sm + GSM_OFF);

    nws[tid] = norm_w[tid];
    ((uint32_t*)sm)[tid] = 0;
    if (tid < 460) ((uint32_t*)sm)[tid + 512] = 0;

#pragma unroll
    for (int j = 0; j < 10; j++) {
        int idx = tid + j * 512;
        int row = idx / 80, c16 = idx % 80;
        uint32_t dst = smb + (uint32_t)(row + 3) * RAW_PITCH + c16 * 16;
        const __half* src = XBC + (size_t)(base + row * stride) * 640 + c16 * 8;
        CP16(dst, src);
    }
    CP_COMMIT();

    if (wid < 8) {
        const int h = wid;
        const float Aneg = -__expf(A_log[h]);
        const float dtb = dt_bias[h];
        const float Dh = Dv[h];
        float v0, v1;
        {
            int t = lane;
            float draw = DT[(size_t)(base + t * stride) * 8 + h] + dtb;
            float dt = (draw > 20.f) ? draw : log1pf(__expf(draw));
            dts[h * 64 + t] = dt; Ddt[h * 64 + t] = Dh / dt;
            v0 = dt * Aneg;
        }
        {
            int t = lane + 32;
            float draw = DT[(size_t)(base + t * stride) * 8 + h] + dtb;
            float dt = (draw > 20.f) ? draw : log1pf(__expf(draw));
            dts[h * 64 + t] = dt; Ddt[h * 64 + t] = Dh / dt;
            v1 = dt * Aneg;
        }
        float a = v0;
#pragma unroll
        for (int o = 1; o < 32; o <<= 1) {
            float u = __shfl_up_sync(0xffffffffu, a, o);
            if (lane >= o) a += u;
        }
        float tot = __shfl_sync(0xffffffffu, a, 31);
        float b = v1;
#pragma unroll
        for (int o = 1; o < 32; o <<= 1) {
            float u = __shfl_up_sync(0xffffffffu, b, o);
            if (lane >= o) b += u;
        }
        b += tot;
        Lc[h * 64 + lane] = a;
        Lc[h * 64 + 32 + lane] = b;
    }
    CP_WAIT(0);
    __syncthreads();

    {
        const int c = tid, hd = c >> 6;
        const float w0 = conv_w[c * 4], w1 = conv_w[c * 4 + 1];
        const float w2 = conv_w[c * 4 + 2], w3 = conv_w[c * 4 + 3];
        const float cb = conv_b[c];
        const bool isbc = (tid < 128);
        const int c2 = 512 + tid;
        float u0 = 0, u1 = 0, u2 = 0, u3 = 0, ub = 0;
        __half* dstBC = (tid < 64) ? (Bm + tid) : (Cm + (tid - 64));
        if (isbc) {
            u0 = conv_w[c2 * 4]; u1 = conv_w[c2 * 4 + 1];
            u2 = conv_w[c2 * 4 + 2]; u3 = conv_w[c2 * 4 + 3];
            ub = conv_b[c2];
        }
        float r0 = 0, r1 = 0, r2 = 0, q0 = 0, q1 = 0, q2 = 0;
#pragma unroll 4
        for (int t = 0; t < SEQ; t++) {
            float cur = __half2float(*(__half*)(sm + (t + 3) * RAW_PITCH + c * 2));
            float v = fmaf(cur, w3, fmaf(r2, w2, fmaf(r1, w1, fmaf(r0, w0, cb))));
            r0 = r1; r1 = r2; r2 = cur;
            v = v / (1.f + __expf(-v));
            XdT[c * 72 + t] = __float2half(v * dts[hd * 64 + t]);
            if (isbc) {
                float cq = __half2float(*(__half*)(sm + (t + 3) * RAW_PITCH + c2 * 2));
                float vq = fmaf(cq, u3, fmaf(q2, u2, fmaf(q1, u1, fmaf(q0, u0, ub))));
                q0 = q1; q1 = q2; q2 = cq;
                vq = vq / (1.f + __expf(-vq));
                dstBC[t * 72] = __float2half(vq);
            }
        }
    }
    __syncthreads();

    const int mi = wid & 3, nj = wid >> 2;
    {
        float acc[2][4];
#pragma unroll
        for (int i = 0; i < 2; i++)
#pragma unroll
            for (int j = 0; j < 4; j++) acc[i][j] = 0.f;
#pragma unroll
        for (int ks = 0; ks < 4; ks++) {
            uint32_t a[4], bq[4];
            ldm4(a,  smb + CM_OFF + (mi * 16 + (lane & 15)) * XDT_PITCH + (lane >> 4) * 16 + ks * 32);
            ldm4(bq, smb + BM_OFF + (nj * 16 + (lane & 15)) * XDT_PITCH + (lane >> 4) * 16 + ks * 32);
            mma16816(acc[0], a, bq[0], bq[2]);
            mma16816(acc[1], a, bq[1], bq[3]);
        }
        const int r = lane >> 2, cc = (lane & 3) * 2;
#pragma unroll
        for (int nt = 0; nt < 2; nt++) {
            int sc = nj * 16 + nt * 8 + cc;
            *(float2*)&G[(mi * 16 + r) * G_PITCH + sc]     = make_float2(acc[nt][0], acc[nt][1]);
            *(float2*)&G[(mi * 16 + r + 8) * G_PITCH + sc] = make_float2(acc[nt][2], acc[nt][3]);
        }
    }

    auto prefetch_z = [&](int h, int buf) {
        int t = tid >> 3, c16 = tid & 7;
        uint32_t dst = smb + ZBUF_OFF + buf * 8192 + t * 128 + c16 * 16;
        const __half* src = Z16 + (size_t)(base + t * stride) * 512 + h * 64 + c16 * 8;
        CP16(dst, src);
        CP_COMMIT();
    };
    prefetch_z(0, 0);
    __syncthreads();

    for (int h = 0; h < 8; h++) {
        if (h < 7) { prefetch_z(h + 1, (h + 1) & 1); CP_WAIT(1); }
        else       { CP_WAIT(0); }

        const float* Lh = Lc + h * 64;
        __half* Gmh = (__half*)(sm + GMH_OFF);
        __half* Gml = (__half*)(sm + GML_OFF);
#pragma unroll
        for (int k = 0; k < 8; k++) {
            int idx = tid + k * 512;
            int t = idx >> 6, sc = idx & 63;
            float w = 0.f;
            if (sc <= t) w = __expf(Lh[t] - Lh[sc]);
            float gm = G[t * G_PITCH + sc] * w;
            if (sc == t) gm += Ddt[h * 64 + t];
            __half hi = __float2half(gm);
            Gmh[t * 72 + sc] = hi;
            Gml[t * 72 + sc] = __float2half(gm - __half2float(hi));
        }
        __syncthreads();

        float acc[2][4];
#pragma unroll
        for (int i = 0; i < 2; i++)
#pragma unroll
            for (int j = 0; j < 4; j++) acc[i][j] = 0.f;
#pragma unroll
        for (int ks = 0; ks < 4; ks++) {
            uint32_t ah[4], al[4], bq[4];
            uint32_t ro = (mi * 16 + (lane & 15)) * XDT_PITCH + (lane >> 4) * 16 + ks * 32;
            ldm4(ah, smb + GMH_OFF + ro);
            ldm4(al, smb + GML_OFF + ro);
            ldm4(bq, smb + XDT_OFF + (uint32_t)(h * 64 + nj * 16 + (lane & 15)) * XDT_PITCH
                        + (lane >> 4) * 16 + ks * 32);
            mma16816(acc[0], ah, bq[0], bq[2]);
            mma16816(acc[1], ah, bq[1], bq[3]);
            mma16816(acc[0], al, bq[0], bq[2]);
            mma16816(acc[1], al, bq[1], bq[3]);
        }
        const int r = lane >> 2, cc = (lane & 3) * 2;
        const char* zbase = sm + ZBUF_OFF + (h & 1) * 8192;
#pragma unroll
        for (int nt = 0; nt < 2; nt++)
#pragma unroll
            for (int rr = 0; rr < 2; rr++) {
                int t = mi * 16 + r + rr * 8;
                int p = nj * 16 + nt * 8 + cc;
                float y0 = acc[nt][rr * 2 + 0], y1 = acc[nt][rr * 2 + 1];
                __half2 zv = *(__half2*)(zbase + t * 128 + p * 2);
                float z0 = __half2float(zv.x), z1 = __half2float(zv.y);
                float g0 = y0 * z0 / (1.f + __expf(-z0));
                float g1 = y1 * z1 / (1.f + __expf(-z1));
                *(__half2*)&gsm[t * GSM_PITCH + h * 64 + p] = __floats2half2_rn(g0, g1);
            }
        __syncthreads();
    }

#pragma unroll
    for (int k = 0; k < 4; k++) {
        int t = wid + k * 16;
        float ss = 0.f;
        float2 gv[8];
#pragma unroll
        for (int j = 0; j < 8; j++) {
            __half2 hv = *(__half2*)&gsm[t * GSM_PITCH + j * 64 + lane * 2];
            float a = __half2float(hv.x), b = __half2float(hv.y);
            gv[j] = make_float2(a, b);
            ss = fmaf(a, a, ss); ss = fmaf(b, b, ss);
        }
#pragma unroll
        for (int o = 16; o; o >>= 1) ss += __shfl_xor_sync(0xffffffffu, ss, o);
        float sinv = rsqrtf(ss * (1.0f / 512.0f) + 1e-5f);
        size_t orow = (size_t)(base + t * stride) * KFIN + ycol;
#pragma unroll
        for (int j = 0; j < 8; j++) {
            int c = j * 64 + lane * 2;
            float a = gv[j].x * sinv * nws[c];
            float b = gv[j].y * sinv * nws[c + 1];
            *(__half2*)&g_Y[orow + c] = __floats2half2_rn(a, b);
        }
    }
}

// ---------------- launch ----------------
extern "C" void kernel_launch(void* const* d_in, const int* in_sizes, int n_in,
                              void* d_out, int out_size)
{
    (void)in_sizes; (void)n_in; (void)out_size;
    const float* x          = (const float*)d_in[0];
    const float* mh_in_w    = (const float*)d_in[1];
    const float* mh_conv_w  = (const float*)d_in[2];
    const float* mh_conv_b  = (const float*)d_in[3];
    const float* mh_dt_bias = (const float*)d_in[4];
    const float* mh_A_log   = (const float*)d_in[5];
    const float* mh_D       = (const float*)d_in[6];
    const float* mh_norm_w  = (const float*)d_in[7];
    const float* mh_out_w   = (const float*)d_in[8];
    const float* mv_in_w    = (const float*)d_in[9];
    const float* mv_conv_w  = (const float*)d_in[10];
    const float* mv_conv_b  = (const float*)d_in[11];
    const float* mv_dt_bias = (const float*)d_in[12];
    const float* mv_A_log   = (const float*)d_in[13];
    const float* mv_D       = (const float*)d_in[14];
    const float* mv_norm_w  = (const float*)d_in[15];
    const float* mv_out_w   = (const float*)d_in[16];
    const float* fc_w       = (const float*)d_in[17];
    const float* fc_b       = (const float*)d_in[18];
    float* out = (float*)d_out;

    __half *Z16h, *Z16v, *XBCh, *XBCv, *Xhi, *Whhi, *Wvhi, *Y, *WcBhi;
    cudaGetSymbolAddress((void**)&Z16h, g_Z16h);
    cudaGetSymbolAddress((void**)&Z16v, g_Z16v);
    cudaGetSymbolAddress((void**)&XBCh, g_XBCh);
    cudaGetSymbolAddress((void**)&XBCv, g_XBCv);
    cudaGetSymbolAddress((void**)&Xhi,  g_Xhi);
    cudaGetSymbolAddress((void**)&Whhi, g_Whhi);
    cudaGetSymbolAddress((void**)&Wvhi, g_Wvhi);
    cudaGetSymbolAddress((void**)&Y,    g_Y);
    cudaGetSymbolAddress((void**)&WcBhi, g_WcBhi);

    cudaFuncSetAttribute(gemm_mma, cudaFuncAttributeMaxDynamicSharedMemorySize, GSMEM);
    cudaFuncSetAttribute(ssd_kernel, cudaFuncAttributeMaxDynamicSharedMemorySize, SSD_SMEM);

    prep_all<<<PREP_GRID, 256>>>(x, mh_in_w, mv_in_w, mh_out_w, mv_out_w, fc_w);

    gemm_mma<<<dim3(NTOK / BMg, NIN / BNg, 2), 256, GSMEM>>>(
        Xhi, Whhi, Wvhi, nullptr,
        Z16h, XBCh, Z16v, XBCv, D_MODEL, 0, nullptr, 1);

    ssd_kernel<<<2 * NSEQ, 512, SSD_SMEM>>>(
        mh_conv_w, mh_conv_b, mh_dt_bias, mh_A_log, mh_D, mh_norm_w,
        mv_conv_w, mv_conv_b, mv_dt_bias, mv_A_log, mv_D, mv_norm_w);

    gemm_mma<<<dim3(NTOK / BMg, D_MODEL / BNg, 1), 256, GSMEM>>>(
        Y, WcBhi, WcBhi, out,
        nullptr, nullptr, nullptr, nullptr, KFIN, D_MODEL, fc_b, 0);
}